// round 17
// baseline (speedup 1.0000x reference)
#include <cuda_runtime.h>
#include <math.h>

#define S_ 256
#define B_ 32
#define H_ 512
#define E_ 256
#define V_ 10000
#define KB 3
#define T_ 32
#define RMAX 96
#define NEGV -1000000000.0f
#define XHW 1280
#define GN 2048
#define NB 148
#define NT 512
#define APAD 98

// ---------------- device state (16B-aligned: float4 paths) ----------------
__device__ __align__(16) float g_encp[S_*B_*H_];
__device__ __align__(16) float g_h[RMAX*H_];
__device__ __align__(16) float g_c[RMAX*H_];
__device__ __align__(16) float g_h2[RMAX*H_];
__device__ __align__(16) float g_c2[RMAX*H_];
__device__ __align__(16) float g_xh[RMAX*XHW];
__device__ __align__(16) float g_z[RMAX*XHW];
__device__ __align__(16) float g_gpart[4*RMAX*GN];
__device__ __align__(16) float g_lpart[4*RMAX*V_];
__device__ __align__(16) float g_logit[RMAX*V_];
__device__ __align__(16) float g_Wcomb[XHW*GN];
__device__ __align__(16) float g_bsum[GN];
__device__ float g_rm[RMAX], g_rl[RMAX];
__device__ float g_cum[RMAX];
__device__ int   g_tok[RMAX], g_eos[RMAX];
__device__ int   g_predsA[T_*RMAX], g_predsB[T_*RMAX];
__device__ int   g_cnt;
__device__ volatile int g_gen;
__device__ int   g_work;          // work-stealing counter (reset at kernel end)

// ---------------- grid barrier ----------------
__device__ __forceinline__ void gsync()
{
    __syncthreads();
    if (threadIdx.x == 0) {
        __threadfence();
        int g = g_gen;
        if (atomicAdd(&g_cnt, 1) == NB - 1) {
            g_cnt = 0;
            __threadfence();
            g_gen = g + 1;
        } else {
            while (g_gen == g) __nanosleep(40);
        }
        __threadfence();
    }
    __syncthreads();
}

__device__ __forceinline__ float sigm(float x) { return 1.f / (1.f + expf(-x)); }

__device__ __forceinline__ float4 ldB4(const float* __restrict__ B, int N, int row, int col)
{
    if (col + 3 < N) return *(const float4*)(B + (size_t)row * N + col);
    float4 v = make_float4(0.f, 0.f, 0.f, 0.f);
    const float* p = B + (size_t)row * N;
    if (col     < N) v.x = p[col];
    if (col + 1 < N) v.y = p[col + 1];
    if (col + 2 < N) v.z = p[col + 2];
    return v;
}

// ------- 96x64 GEMM tile, 512 threads, TM=3 TN=4, double-buffered ---------
__device__ void gtile(int M, int N, int K, int kbeg, int kend, int col0,
                      const float* __restrict__ A, const float* __restrict__ B,
                      float* __restrict__ out, const float* __restrict__ bias,
                      float* sm)
{
    float*  As  = sm;                          // [16][APAD]
    float4* Bs4 = (float4*)(sm + 16 * APAD);   // [16][16] float4 (sm+1568: 16B ok)
    int tid = threadIdx.x, tr = tid >> 4, tc = tid & 15;
    float acc[3][4];
#pragma unroll
    for (int i = 0; i < 3; i++)
#pragma unroll
        for (int j = 0; j < 4; j++) acc[i][j] = 0.f;

    int am[3], ak[3];
#pragma unroll
    for (int l = 0; l < 3; l++) { int idx = tid + l * NT; am[l] = idx >> 4; ak[l] = idx & 15; }
    int bk = tid >> 4, bn = (tid & 15) * 4;
    bool bld = (tid < 256);

    float ra[3]; float4 rb = make_float4(0.f,0.f,0.f,0.f);
#pragma unroll
    for (int l = 0; l < 3; l++)
        ra[l] = (am[l] < M) ? A[am[l] * K + kbeg + ak[l]] : 0.f;
    if (bld) rb = ldB4(B, N, kbeg + bk, col0 + bn);

    for (int k0 = kbeg; k0 < kend; k0 += 16) {
#pragma unroll
        for (int l = 0; l < 3; l++) As[ak[l] * APAD + am[l]] = ra[l];
        if (bld) Bs4[bk * 16 + (tid & 15)] = rb;
        __syncthreads();

        int kn = k0 + 16;
        if (kn < kend) {
#pragma unroll
            for (int l = 0; l < 3; l++)
                ra[l] = (am[l] < M) ? A[am[l] * K + kn + ak[l]] : 0.f;
            if (bld) rb = ldB4(B, N, kn + bk, col0 + bn);
        }
#pragma unroll
        for (int kk = 0; kk < 16; kk++) {
            const float* arow = As + kk * APAD + tr * 3;
            float a0 = arow[0], a1 = arow[1], a2 = arow[2];
            float4 bv = Bs4[kk * 16 + tc];
            acc[0][0] += a0 * bv.x; acc[0][1] += a0 * bv.y;
            acc[0][2] += a0 * bv.z; acc[0][3] += a0 * bv.w;
            acc[1][0] += a1 * bv.x; acc[1][1] += a1 * bv.y;
            acc[1][2] += a1 * bv.z; acc[1][3] += a1 * bv.w;
            acc[2][0] += a2 * bv.x; acc[2][1] += a2 * bv.y;
            acc[2][2] += a2 * bv.z; acc[2][3] += a2 * bv.w;
        }
        __syncthreads();
    }
#pragma unroll
    for (int i = 0; i < 3; i++) {
        int gm = tr * 3 + i;
        if (gm >= M) continue;
        int gn = col0 + tc * 4;
        float4 v = make_float4(acc[i][0], acc[i][1], acc[i][2], acc[i][3]);
        if (gn + 3 < N) {
            if (bias) {
                const float4 b4 = *(const float4*)(bias + gn);
                v.x += b4.x; v.y += b4.y; v.z += b4.z; v.w += b4.w;
            }
            *(float4*)(out + (size_t)gm * N + gn) = v;
        } else {
            float vv[4] = {v.x, v.y, v.z, v.w};
            for (int j = 0; j < 4; j++)
                if (gn + j < N) {
                    float o = vv[j];
                    if (bias) o += bias[gn + j];
                    out[(size_t)gm * N + gn + j] = o;
                }
        }
    }
}

// -------- total-order helpers for top-3 --------
__device__ __forceinline__ bool cbetter(float av, int ai, float bv, int bi)
{ return (av > bv) || (av == bv && ai < bi); }

__device__ __forceinline__ void t3ins(float v, int i, float* tv, int* ti)
{
    if (cbetter(v, i, tv[2], ti[2])) {
        if (cbetter(v, i, tv[1], ti[1])) {
            tv[2] = tv[1]; ti[2] = ti[1];
            if (cbetter(v, i, tv[0], ti[0])) {
                tv[1] = tv[0]; ti[1] = ti[0]; tv[0] = v; ti[0] = i;
            } else { tv[1] = v; ti[1] = i; }
        } else { tv[2] = v; ti[2] = i; }
    }
}

__device__ __forceinline__ void t3merge(float* av, int* ai, const float* bv, const int* bi)
{
    float rv[3]; int ri[3];
    int pa = 0, pb = 0;
#pragma unroll
    for (int o = 0; o < 3; o++) {
        if (cbetter(av[pa], ai[pa], bv[pb], bi[pb])) { rv[o] = av[pa]; ri[o] = ai[pa]; pa++; }
        else                                          { rv[o] = bv[pb]; ri[o] = bi[pb]; pb++; }
    }
#pragma unroll
    for (int o = 0; o < 3; o++) { av[o] = rv[o]; ai[o] = ri[o]; }
}

// ---- P_A: embed + in-block pp + score + softmax + ctx (one block/row) ----
__device__ __noinline__ void attn_phase(int r, int b, int t,
                                        const float* __restrict__ Wp,
                                        const float* __restrict__ Wv,
                                        const float* __restrict__ amask,
                                        const float* __restrict__ emb,
                                        const float* __restrict__ enc,
                                        float* sm)
{
    int tid = threadIdx.x;
    float* hs   = sm;          // 512
    float* pps  = sm + 512;    // 512
    float* wv   = sm + 1024;   // 512
    float* srow = sm + 1536;   // 256
    float* tre  = sm + 1792;   // 256
    float* sa   = sm + 2048;   // 256

    hs[tid] = g_h[r * H_ + tid];            // NT == H_
    wv[tid] = Wv[tid];
    if (tid < E_) {
        int tk = (t == 0) ? 1 : g_tok[r];
        float ev = emb[tk * E_ + tid];
        g_xh[r * XHW + tid] = ev;
        g_z[r * XHW + tid] = ev;
    }
    if (t == 0) g_xh[r * XHW + E_ + H_ + tid] = hs[tid];
    __syncthreads();

    // pp: 256 threads, each two columns (float2 over Wp), 4-deep accumulators
    if (tid < 256) {
        int j = tid * 2;
        float a0=0.f,a1=0.f,a2=0.f,a3=0.f, b0=0.f,b1=0.f,b2=0.f,b3=0.f;
#pragma unroll 4
        for (int k = 0; k < H_; k += 4) {
            float2 w0 = *(const float2*)(Wp + (size_t)k * H_ + j);
            float2 w1 = *(const float2*)(Wp + (size_t)(k+1) * H_ + j);
            float2 w2 = *(const float2*)(Wp + (size_t)(k+2) * H_ + j);
            float2 w3 = *(const float2*)(Wp + (size_t)(k+3) * H_ + j);
            float h0 = hs[k], h1 = hs[k+1], h2 = hs[k+2], h3 = hs[k+3];
            a0 += h0 * w0.x; b0 += h0 * w0.y;
            a1 += h1 * w1.x; b1 += h1 * w1.y;
            a2 += h2 * w2.x; b2 += h2 * w2.y;
            a3 += h3 * w3.x; b3 += h3 * w3.y;
        }
        pps[j]     = (a0 + a1) + (a2 + a3);
        pps[j + 1] = (b0 + b1) + (b2 + b3);
    }
    __syncthreads();

    int w = tid >> 5, lane = tid & 31;       // 16 warps
    for (int si = 0; si < 16; si++) {
        int s = w * 16 + si;
        const float* ep = &g_encp[(s * B_ + b) * H_];
        float a = 0.f;
#pragma unroll 4
        for (int k2 = 0; k2 < 16; k2++) {
            int hh = lane + k2 * 32;
            a += tanhf(pps[hh] + ep[hh]) * wv[hh];
        }
        for (int o = 16; o; o >>= 1) a += __shfl_xor_sync(0xffffffffu, a, o);
        if (lane == 0) {
            float mv = amask[b * S_ + s];
            srow[s] = (mv == 0.f) ? NEGV : a;
        }
    }
    __syncthreads();
    float v = (tid < S_) ? srow[tid] : NEGV;
    if (tid < S_) tre[tid] = v;
    __syncthreads();
    for (int o = 128; o; o >>= 1) {
        if (tid < o) tre[tid] = fmaxf(tre[tid], tre[tid + o]);
        __syncthreads();
    }
    float m = tre[0]; __syncthreads();
    float e = expf(v - m);
    if (tid < S_) tre[tid] = e;
    __syncthreads();
    for (int o = 128; o; o >>= 1) {
        if (tid < o) tre[tid] += tre[tid + o];
        __syncthreads();
    }
    float denom = tre[0]; __syncthreads();
    if (tid < S_) sa[tid] = e / denom;
    __syncthreads();
    {
        int hh = tid;
        float a = 0.f;
#pragma unroll 8
        for (int s = 0; s < S_; s++)
            a += sa[s] * enc[(s * B_ + b) * H_ + hh];
        g_xh[r * XHW + E_ + hh] = a;
        g_z[r * XHW + E_ + H_ + hh] = a;
    }
}

__device__ __noinline__ void lse_phase(int r, const float* __restrict__ bc, float* sm)
{
    int tid = threadIdx.x;
    const float* l0 = &g_lpart[(0 * 96 + r) * V_];
    const float* l1 = &g_lpart[(1 * 96 + r) * V_];
    const float* l2 = &g_lpart[(2 * 96 + r) * V_];
    const float* l3 = &g_lpart[(3 * 96 + r) * V_];
    float* lo = &g_logit[r * V_];
    float mx = -3.4e38f;
    for (int v = tid; v < V_; v += NT) {
        float c = l0[v] + l1[v] + l2[v] + l3[v] + bc[v];
        lo[v] = c;
        mx = fmaxf(mx, c);
    }
    sm[tid] = mx; __syncthreads();
    for (int o = 256; o; o >>= 1) {
        if (tid < o) sm[tid] = fmaxf(sm[tid], sm[tid + o]);
        __syncthreads();
    }
    float m = sm[0]; __syncthreads();
    float s = 0.f;
    for (int v = tid; v < V_; v += NT)
        s += expf(lo[v] - m);
    sm[tid] = s; __syncthreads();
    for (int o = 256; o; o >>= 1) {
        if (tid < o) sm[tid] += sm[tid + o];
        __syncthreads();
    }
    if (tid == 0) { g_rm[r] = m; g_rl[r] = logf(sm[0]); }
    __syncthreads();
}

__device__ __noinline__ void topk_phase(int b, int t, int mode, float* sm,
                                        int* selSrc, int* selTok, int* eosOld)
{
    int tid = threadIdx.x;
    float* mv = sm;                      // 512*3
    int*   mi = (int*)(sm + 1536);       // 512*3
    float tv[3] = {-3.4e38f, -3.4e38f, -3.4e38f};
    int   ti[3] = {0x7fffffff, 0x7fffffff, 0x7fffffff};
    int nk = mode ? KB : 1;
    for (int k = 0; k < nk; k++) {
        int row = mode ? b * KB + k : b;
        int base = k * V_;
        int reos = mode ? g_eos[row] : 0;
        float rcum = mode ? g_cum[row] : 0.f;
        float sub = g_rm[row] + g_rl[row];
        const float* lo = &g_logit[row * V_];
        if (reos) {
            for (int v = tid; v < V_; v += NT)
                t3ins(rcum + ((v == 1) ? 0.f : NEGV), base + v, tv, ti);
        } else {
            for (int v = tid; v < V_; v += NT)
                t3ins(rcum + (lo[v] - sub), base + v, tv, ti);
        }
    }
#pragma unroll
    for (int o = 0; o < 3; o++) { mv[tid * 3 + o] = tv[o]; mi[tid * 3 + o] = ti[o]; }
    __syncthreads();
    for (int off = 256; off; off >>= 1) {
        if (tid < off) {
            float bv2[3]; int bi2[3];
            float av2[3]; int ai2[3];
#pragma unroll
            for (int o = 0; o < 3; o++) {
                bv2[o] = mv[(tid + off) * 3 + o]; bi2[o] = mi[(tid + off) * 3 + o];
                av2[o] = mv[tid * 3 + o];         ai2[o] = mi[tid * 3 + o];
            }
            t3merge(av2, ai2, bv2, bi2);
#pragma unroll
            for (int o = 0; o < 3; o++) { mv[tid * 3 + o] = av2[o]; mi[tid * 3 + o] = ai2[o]; }
        }
        __syncthreads();
    }
    if (tid < KB) eosOld[tid] = mode ? g_eos[b * KB + tid] : 0;
    __syncthreads();
    if (tid < KB) {
        int p = tid;
        int i = mi[p];
        int k = mode ? i / V_ : 0;
        int v = i - k * V_;
        int nr = b * KB + p;
        int src = mode ? b * KB + k : b;
        selSrc[p] = src; selTok[p] = v;
        g_tok[nr] = v;
        g_cum[nr] = mv[p];
        g_eos[nr] = mode ? ((eosOld[k] || v == 1) ? 1 : 0) : ((v == 1) ? 1 : 0);
    }
    __syncthreads();
    for (int p = 0; p < KB; p++) {
        int nr = b * KB + p, src = selSrc[p];
        {
            int j = tid;
            float hv = g_h2[src * H_ + j];
            g_h[nr * H_ + j] = hv;
            g_c[nr * H_ + j] = g_c2[src * H_ + j];
            g_xh[nr * XHW + E_ + H_ + j] = hv;
        }
    }
    int* pin  = (t & 1) ? g_predsA : g_predsB;
    int* pout = (t & 1) ? g_predsB : g_predsA;
    if (tid < T_ * KB) {
        int tt = tid / KB, p = tid % KB;
        int nr = b * KB + p;
        int val;
        if (tt == t) val = selTok[p];
        else if (t == 0) val = 0;
        else val = pin[tt * RMAX + selSrc[p]];
        pout[tt * RMAX + nr] = val;
    }
}

// ---------------- persistent megakernel ----------------
__global__ void __launch_bounds__(NT, 1)
mega(const float* __restrict__ enc, const float* __restrict__ last_h,
     const float* __restrict__ last_c, const float* __restrict__ amask,
     const float* __restrict__ emb, const float* __restrict__ Wp,
     const float* __restrict__ We, const float* __restrict__ Wv,
     const float* __restrict__ Wih, const float* __restrict__ Whh,
     const float* __restrict__ bih, const float* __restrict__ bhh,
     const float* __restrict__ Wc, const float* __restrict__ bc,
     const float* __restrict__ Winit, const float* __restrict__ binit,
     float* __restrict__ out, int out_size)
{
    __shared__ __align__(16) float sm[3104];
    __shared__ int   selSrc[KB], selTok[KB], eosOld[KB];
    __shared__ int   s_u;
    int bid = blockIdx.x, tid = threadIdx.x;
    int wbase = 0;

    // ---------- P0: enc_proj + h0 + c0 (stolen) + Wcomb/bsum ----------
    for (;;) {
        if (tid == 0) s_u = atomicAdd(&g_work, 1);
        __syncthreads();
        int u = s_u;
        if (u >= 704) break;
        if (u < 688) {
            int mt = u >> 3, col0 = (u & 7) * 64;
            int row0 = mt * 96;
            int M = (S_ * B_ - row0 < 96) ? (S_ * B_ - row0) : 96;
            gtile(M, H_, H_, 0, H_, col0, enc + row0 * H_, We, g_encp + row0 * H_, 0, sm);
        } else if (u < 696) {
            gtile(B_, H_, H_, 0, H_, (u - 688) * 64, last_h + B_ * H_, Winit, g_h, binit, sm);
        } else {
            gtile(B_, H_, H_, 0, H_, (u - 696) * 64, last_c + B_ * H_, Winit, g_c, binit, sm);
        }
        __syncthreads();
    }
    wbase = 704 + NB;
    for (int idx = bid * NT + tid; idx < XHW * GN; idx += NB * NT) {
        int k = idx >> 11, n = idx & (GN - 1);
        g_Wcomb[idx] = (k < E_ + H_) ? Wih[k * GN + n] : Whh[(k - (E_ + H_)) * GN + n];
    }
    for (int idx = bid * NT + tid; idx < GN; idx += NB * NT)
        g_bsum[idx] = bih[idx] + bhh[idx];
    gsync();

    for (int t = 0; t < T_; t++) {
        int R   = (t == 0) ? B_ : RMAX;
        int div = (t == 0) ? 1 : KB;
        int mode = (t == 0) ? 0 : 1;

        // P_A: embed + pp + attention
        if (bid < R) attn_phase(bid, bid / div, t, Wp, Wv, amask, emb, enc, sm);
        gsync();

        // P_B: gates split4 (static: 128 units, one per block)
        if (bid < 128) {
            int col0 = (bid & 31) * 64, zz = bid >> 5;
            gtile(R, GN, XHW, zz * 320, zz * 320 + 320, col0, g_xh, g_Wcomb,
                  g_gpart + zz * 96 * GN, 0, sm);
        }
        gsync();

        // P_C: LSTM elementwise
        if (bid < R) {
            int r = bid;
            int hh = tid;
            float gi = g_bsum[hh], gf = g_bsum[H_ + hh];
            float gg = g_bsum[2 * H_ + hh], go = g_bsum[3 * H_ + hh];
#pragma unroll
            for (int zz = 0; zz < 4; zz++) {
                const float* p = &g_gpart[(zz * 96 + r) * GN];
                gi += p[hh]; gf += p[H_ + hh]; gg += p[2 * H_ + hh]; go += p[3 * H_ + hh];
            }
            float cc = sigm(gf) * g_c[r * H_ + hh] + sigm(gi) * tanhf(gg);
            float h2 = sigm(go) * tanhf(cc);
            g_c2[r * H_ + hh] = cc;
            g_h2[r * H_ + hh] = h2;
            g_z[r * XHW + E_ + hh] = h2;
        }
        gsync();

        // P_D: logits split4, work-stolen (628 units)
        for (;;) {
            if (tid == 0) s_u = atomicAdd(&g_work, 1);
            __syncthreads();
            int u = s_u - wbase;
            if (u >= 628) break;
            int col = u % 157, zz = u / 157;
            gtile(R, V_, XHW, zz * 320, zz * 320 + 320, col * 64, g_z, Wc,
                  g_lpart + zz * 96 * V_, 0, sm);
            __syncthreads();
        }
        wbase += 628 + NB;
        gsync();

        // P_E: lse (1 or 3 rows) + topk + gather, one block per batch
        if (bid < B_) {
            int nk = mode ? KB : 1;
            for (int ri = 0; ri < nk; ri++)
                lse_phase(mode ? bid * KB + ri : bid, bc, sm);
            topk_phase(bid, t, mode, sm, selSrc, selTok, eosOld);
        }
        gsync();
    }

    // ---------- writeout ----------
    for (int i = bid * NT + tid; i < out_size; i += NB * NT) {
        const int total = T_ * B_ + B_ * KB;
        if (i < T_ * B_) {
            int t = i / B_, b = i % B_;
            out[i] = (float)g_predsB[t * RMAX + b * KB];
        } else if (i < total) {
            out[i] = g_cum[i - T_ * B_];
        } else {
            out[i] = 0.f;
        }
    }
    __syncthreads();
    if (bid == 0 && tid == 0) g_work = 0;   // reset for next replay
}

extern "C" void kernel_launch(void* const* d_in, const int* in_sizes, int n_in,
                              void* d_out, int out_size)
{
    const float* enc    = (const float*)d_in[0];
    const float* last_h = (const float*)d_in[1];
    const float* last_c = (const float*)d_in[2];
    const float* amask  = (const float*)d_in[3];
    /* d_in[4] = indices (unused) */
    const float* emb    = (const float*)d_in[5];
    const float* Wp     = (const float*)d_in[6];
    const float* We     = (const float*)d_in[7];
    const float* Wv     = (const float*)d_in[8];
    const float* W_ih   = (const float*)d_in[9];
    const float* W_hh   = (const float*)d_in[10];
    const float* b_ih   = (const float*)d_in[11];
    const float* b_hh   = (const float*)d_in[12];
    const float* Wc     = (const float*)d_in[13];
    const float* bc     = (const float*)d_in[14];
    const float* W_init = (const float*)d_in[15];
    const float* b_init = (const float*)d_in[16];

    mega<<<NB, NT>>>(enc, last_h, last_c, amask, emb, Wp, We, Wv,
                     W_ih, W_hh, b_ih, b_hh, Wc, bc, W_init, b_init,
                     (float*)d_out, out_size);
}